// round 5
// baseline (speedup 1.0000x reference)
#include <cuda_runtime.h>
#include <cuda_bf16.h>
#include <cstdint>

#define BB 32
#define SS 512
#define DD 768
#define SQ 511
#define NROWS (BB*SQ)
#define NEG_INF __int_as_float(0xff800000)

#define CHUNKS 36          // K = 3*768 = 2304, chunks of 64
#define BLK_U4 1024        // 128 rows * 64 bf16 * 2B / 16B
#define TAU 4e-3f

// prepped tiles: [b][tile(0..3)][chunk][128 rows x 64 bf16, swizzled]
__device__ uint4 g_Apre[(size_t)BB * 4 * CHUNKS * BLK_U4];
__device__ uint4 g_Bpre[(size_t)BB * 4 * CHUNKS * BLK_U4];
__device__ float g_invn[NROWS];
__device__ float g_pv1[NROWS * 4];
__device__ int   g_pj1[NROWS * 4];
__device__ float g_pv2[NROWS * 4];
__device__ int   g_idx[NROWS];
__device__ int   g_queue[NROWS];
__device__ int   g_qcnt;
__device__ float g_txt_sum;
__device__ float g_img_sum;
__device__ int   g_valid;

__device__ __forceinline__ uint32_t smem_u32(const void* p) {
    uint32_t a;
    asm("{ .reg .u64 t; cvta.to.shared.u64 t, %1; cvt.u32.u64 %0, t; }"
        : "=r"(a) : "l"(p));
    return a;
}

// ============================ init ============================

__global__ void k_init() {
    g_txt_sum = 0.f; g_img_sum = 0.f; g_valid = 0; g_qcnt = 0;
}

// ============================ invnorm ============================

__global__ void k_invnorm(const float* __restrict__ target) {
    int row = blockIdx.x * (blockDim.x >> 5) + (threadIdx.x >> 5);
    if (row >= NROWS) return;
    int lane = threadIdx.x & 31;
    int b = row / SQ, j = row % SQ;
    const float4* p = reinterpret_cast<const float4*>(
        target + (size_t)b * SS * DD + (size_t)(j + 1) * DD);
    float s = 0.f;
#pragma unroll
    for (int it = 0; it < DD / 128; it++) {
        float4 v = p[lane + it * 32];
        s += v.x * v.x + v.y * v.y + v.z * v.z + v.w * v.w;
    }
#pragma unroll
    for (int o = 16; o > 0; o >>= 1) s += __shfl_xor_sync(0xffffffffu, s, o);
    if (lane == 0) g_invn[row] = rsqrtf(s);
}

// ============================ prep ============================
// 3 split groups: A = [hi, hi, mid], B = [hi, mid, hi] -> hh + hm + mh.

__device__ __forceinline__ uint4 pack8(const unsigned short* u) {
    uint4 v;
    v.x = (uint32_t)u[0] | ((uint32_t)u[1] << 16);
    v.y = (uint32_t)u[2] | ((uint32_t)u[3] << 16);
    v.z = (uint32_t)u[4] | ((uint32_t)u[5] << 16);
    v.w = (uint32_t)u[6] | ((uint32_t)u[7] << 16);
    return v;
}

__device__ __forceinline__ void split8(const float* x, uint4& vh, uint4& vm) {
    unsigned short h[8], m[8];
#pragma unroll
    for (int q = 0; q < 8; q++) {
        __nv_bfloat16 bh = __float2bfloat16(x[q]);
        float r1 = x[q] - __bfloat162float(bh);
        __nv_bfloat16 bm = __float2bfloat16(r1);
        h[q] = __bfloat16_as_ushort(bh);
        m[q] = __bfloat16_as_ushort(bm);
    }
    vh = pack8(h); vm = pack8(m);
}

__device__ __forceinline__ void prep_store(uint4* base, int r, int c, int kg, uint4 v) {
    int tile = r >> 7, row = r & 127;
    base[((size_t)tile * CHUNKS + c) * BLK_U4 + row * 8 + (kg ^ (row & 7))] = v;
}

__global__ void k_prep_A(const float* __restrict__ text) {
    int item = blockIdx.x * blockDim.x + threadIdx.x;   // BB*512*96
    if (item >= BB * 512 * 96) return;
    int ks = item % 96;
    int r  = (item / 96) & 511;
    int b  = item / (96 * 512);
    float x[8];
    if (r < SQ) {
        const float* src = text + ((size_t)b * SS + r + 1) * DD + ks * 8;
#pragma unroll
        for (int q = 0; q < 8; q++) x[q] = src[q];
    } else {
#pragma unroll
        for (int q = 0; q < 8; q++) x[q] = 0.f;
    }
    uint4 vh, vm;
    split8(x, vh, vm);
    uint4* base = g_Apre + (size_t)b * 4 * CHUNKS * BLK_U4;
#pragma unroll
    for (int g = 0; g < 3; g++) {
        uint4 v = (g < 2) ? vh : vm;      // A: hi, hi, mid
        int k6 = g * DD + ks * 8;
        prep_store(base, r, k6 >> 6, (k6 & 63) >> 3, v);
    }
}

__global__ void k_prep_B(const float* __restrict__ target) {
    int item = blockIdx.x * blockDim.x + threadIdx.x;
    if (item >= BB * 512 * 96) return;
    int ks = item % 96;
    int r  = (item / 96) & 511;
    int b  = item / (96 * 512);
    float x[8];
    if (r < SQ) {
        const float* src = target + ((size_t)b * SS + r + 1) * DD + ks * 8;
#pragma unroll
        for (int q = 0; q < 8; q++) x[q] = src[q];
    } else {
#pragma unroll
        for (int q = 0; q < 8; q++) x[q] = 0.f;
    }
    uint4 vh, vm;
    split8(x, vh, vm);
    uint4* base = g_Bpre + (size_t)b * 4 * CHUNKS * BLK_U4;
#pragma unroll
    for (int g = 0; g < 3; g++) {
        uint4 v = (g == 1) ? vm : vh;     // B: hi, mid, hi
        int k6 = g * DD + ks * 8;
        prep_store(base, r, k6 >> 6, (k6 & 63) >> 3, v);
    }
}

// ============================ GEMM + top-2 argmax ============================
// CTA: 128x128 tile; 8 warps of 64x32; BK=64 double-buffered cp.async.
// grid: x = itile*4 + jtile (16), y = b (32).

#define SMEM_DYN (65536 + 512)

#define LDSM_X4(r0, r1, r2, r3, addr) \
    asm volatile("ldmatrix.sync.aligned.m8n8.x4.shared.b16 {%0,%1,%2,%3}, [%4];" \
                 : "=r"(r0), "=r"(r1), "=r"(r2), "=r"(r3) : "r"(addr))

#define MMA16816(c, a, b0, b1) \
    asm volatile("mma.sync.aligned.m16n8k16.row.col.f32.bf16.bf16.f32 " \
                 "{%0,%1,%2,%3}, {%4,%5,%6,%7}, {%8,%9}, {%0,%1,%2,%3};" \
                 : "+f"((c)[0]), "+f"((c)[1]), "+f"((c)[2]), "+f"((c)[3]) \
                 : "r"((a)[0]), "r"((a)[1]), "r"((a)[2]), "r"((a)[3]), \
                   "r"(b0), "r"(b1))

__global__ __launch_bounds__(256, 2) void k_gemm() {
    extern __shared__ __align__(16) char sm[];
    uint32_t smb = smem_u32(sm);
    int tid = threadIdx.x, lane = tid & 31, wid = tid >> 5;
    int bx = blockIdx.x;
    int itile = bx >> 2, jtile = bx & 3;
    int b = blockIdx.y;
    int warpM = (wid & 1) * 64, warpN = (wid >> 1) * 32;

    float* Inv = (float*)(sm + 65536);
    if (tid < 128) {
        int j = jtile * 128 + tid;
        Inv[tid] = (j < SQ) ? g_invn[b * SQ + j] : 0.f;
    }

    const char* Asrc = (const char*)(g_Apre + (size_t)(b * 4 + itile) * CHUNKS * BLK_U4);
    const char* Bsrc = (const char*)(g_Bpre + (size_t)(b * 4 + jtile) * CHUNKS * BLK_U4);

    float acc[4][4][4];
#pragma unroll
    for (int mt = 0; mt < 4; mt++)
#pragma unroll
        for (int n8 = 0; n8 < 4; n8++)
#pragma unroll
            for (int e = 0; e < 4; e++) acc[mt][n8][e] = 0.f;

#define STAGE_COPY(c, s) do {                                                   \
    uint32_t dA = smb + (s) * 32768 + tid * 16;                                 \
    const char* gA = Asrc + (size_t)(c) * 16384 + tid * 16;                     \
    const char* gB = Bsrc + (size_t)(c) * 16384 + tid * 16;                     \
    _Pragma("unroll")                                                           \
    for (int it = 0; it < 4; it++) {                                            \
        asm volatile("cp.async.cg.shared.global [%0], [%1], 16;"                \
                     :: "r"(dA + it * 4096), "l"(gA + it * 4096));              \
        asm volatile("cp.async.cg.shared.global [%0], [%1], 16;"                \
                     :: "r"(dA + 16384 + it * 4096), "l"(gB + it * 4096));      \
    }                                                                           \
    asm volatile("cp.async.commit_group;");                                     \
} while (0)

    STAGE_COPY(0, 0);
    STAGE_COPY(1, 1);

    int lrow = lane & 15, khalf = lane >> 4;
    int bg8 = lane >> 3, bl8 = lane & 7;
    int bRow0 = warpN + ((bg8 >> 1) << 3) + bl8;
    int bKg = bg8 & 1;

    for (int c = 0; c < CHUNKS; c++) {
        if (c < CHUNKS - 1) asm volatile("cp.async.wait_group 1;");
        else                asm volatile("cp.async.wait_group 0;");
        __syncthreads();
        uint32_t aB = smb + (c & 1) * 32768;
        uint32_t bBs = aB + 16384;
#pragma unroll
        for (int ks = 0; ks < 4; ks++) {
            uint32_t a[4][4];
#pragma unroll
            for (int mt = 0; mt < 4; mt++) {
                int row = warpM + mt * 16 + lrow;
                int kg  = ks * 2 + khalf;
                uint32_t ad = aB + row * 128 + ((kg ^ (row & 7)) << 4);
                LDSM_X4(a[mt][0], a[mt][1], a[mt][2], a[mt][3], ad);
            }
            uint32_t bb[2][4];
#pragma unroll
            for (int nb = 0; nb < 2; nb++) {
                int row = bRow0 + nb * 16;
                int kg  = ks * 2 + bKg;
                uint32_t ad = bBs + row * 128 + ((kg ^ (row & 7)) << 4);
                LDSM_X4(bb[nb][0], bb[nb][1], bb[nb][2], bb[nb][3], ad);
            }
#pragma unroll
            for (int mt = 0; mt < 4; mt++)
#pragma unroll
                for (int n8 = 0; n8 < 4; n8++)
                    MMA16816(acc[mt][n8], a[mt],
                             bb[n8 >> 1][(n8 & 1) * 2],
                             bb[n8 >> 1][(n8 & 1) * 2 + 1]);
        }
        __syncthreads();
        if (c + 2 < CHUNKS) STAGE_COPY(c + 2, c & 1);
    }
#undef STAGE_COPY

    // epilogue: per-row top-2 within this 128-j tile, no atomics.
    float* sv1 = (float*)sm;             // [128][4]
    int*   sj1 = (int*)(sm + 2048);      // [128][4]
    float* sv2 = (float*)(sm + 4096);    // [128][4]

    int gid = lane >> 2, tig = lane & 3;
#pragma unroll
    for (int mt = 0; mt < 4; mt++) {
#pragma unroll
        for (int rh = 0; rh < 2; rh++) {
            int iloc = warpM + mt * 16 + gid + rh * 8;
            float v1 = NEG_INF, v2 = NEG_INF;
            int j1 = 1 << 30;
#pragma unroll
            for (int n8 = 0; n8 < 4; n8++) {
#pragma unroll
                for (int e = 0; e < 2; e++) {
                    int jloc = warpN + n8 * 8 + tig * 2 + e;
                    int j = jtile * 128 + jloc;
                    float v = (j < SQ) ? acc[mt][n8][rh * 2 + e] * Inv[jloc]
                                       : NEG_INF;
                    if (v > v1) { v2 = v1; v1 = v; j1 = j; }
                    else if (v > v2) v2 = v;
                }
            }
#pragma unroll
            for (int o = 1; o <= 2; o <<= 1) {
                float ov1 = __shfl_xor_sync(0xffffffffu, v1, o);
                float ov2 = __shfl_xor_sync(0xffffffffu, v2, o);
                int   oj  = __shfl_xor_sync(0xffffffffu, j1, o);
                if (ov1 > v1 || (ov1 == v1 && oj < j1)) {
                    v2 = fmaxf(v1, ov2); v1 = ov1; j1 = oj;
                } else {
                    v2 = fmaxf(v2, ov1);
                }
            }
            if (tig == 0) {
                int s = iloc * 4 + (wid >> 1);
                sv1[s] = v1; sj1[s] = j1; sv2[s] = v2;
            }
        }
    }
    __syncthreads();

    if (tid < 128) {
        float v1 = NEG_INF, v2 = NEG_INF;
        int j1 = 1 << 30;
#pragma unroll
        for (int q = 0; q < 4; q++) {
            float a1 = sv1[tid * 4 + q];
            float a2 = sv2[tid * 4 + q];
            int   aj = sj1[tid * 4 + q];
            if (a1 > v1 || (a1 == v1 && aj < j1)) {
                v2 = fmaxf(v1, a2); v1 = a1; j1 = aj;
            } else {
                v2 = fmaxf(v2, a1);
            }
        }
        int i = itile * 128 + tid;
        if (i < SQ) {
            int s = (b * SQ + i) * 4 + jtile;
            g_pv1[s] = v1; g_pj1[s] = j1; g_pv2[s] = v2;
        }
    }
}

// merge 4 jtile partials per row; enqueue ambiguous rows.
__global__ void k_merge() {
    int n = blockIdx.x * blockDim.x + threadIdx.x;
    if (n >= NROWS) return;
    float v1 = NEG_INF, v2 = NEG_INF;
    int j1 = 1 << 30;
#pragma unroll
    for (int q = 0; q < 4; q++) {
        float a1 = g_pv1[n * 4 + q];
        float a2 = g_pv2[n * 4 + q];
        int   aj = g_pj1[n * 4 + q];
        if (a1 > v1 || (a1 == v1 && aj < j1)) {
            v2 = fmaxf(v1, a2); v1 = a1; j1 = aj;
        } else {
            v2 = fmaxf(v2, a1);
        }
    }
    g_idx[n] = j1;
    if (v1 - v2 < TAU) {
        int slot = atomicAdd(&g_qcnt, 1);
        g_queue[slot] = n;
    }
}

// exact fp32 rescore for ambiguous rows: one CTA per queue entry.
__global__ void k_rescore(const float* __restrict__ text,
                          const float* __restrict__ target) {
    __shared__ float txs[DD];
    __shared__ float wv[4];
    __shared__ int   wj[4];
    int cnt = g_qcnt;
    for (int q = blockIdx.x; q < cnt; q += gridDim.x) {
        int row = g_queue[q];
        int b = row / SQ, i = row % SQ;
        __syncthreads();
        for (int d = threadIdx.x; d < DD; d += 128)
            txs[d] = text[((size_t)b * SS + i + 1) * DD + d];
        __syncthreads();
        int wid = threadIdx.x >> 5, lane = threadIdx.x & 31;
        float best = NEG_INF;
        int bj = 0;
        for (int j = wid; j < SQ; j += 4) {
            const float* tg = target + ((size_t)b * SS + j + 1) * DD;
            float s = 0.f;
            for (int d = lane; d < DD; d += 32) s += txs[d] * tg[d];
#pragma unroll
            for (int o = 16; o > 0; o >>= 1) s += __shfl_xor_sync(0xffffffffu, s, o);
            float v = s * g_invn[b * SQ + j];
            if (v > best) { best = v; bj = j; }
        }
        if (lane == 0) { wv[wid] = best; wj[wid] = bj; }
        __syncthreads();
        if (threadIdx.x == 0) {
            float B = wv[0]; int J = wj[0];
#pragma unroll
            for (int w = 1; w < 4; w++)
                if (wv[w] > B || (wv[w] == B && wj[w] < J)) { B = wv[w]; J = wj[w]; }
            g_idx[row] = J;
        }
    }
}

// ============================ losses ============================

__global__ void k_imgloss(const float* __restrict__ image,
                          const float* __restrict__ target) {
    const int N4 = BB * SS * DD / 4;
    float s = 0.f;
    for (int i = blockIdx.x * blockDim.x + threadIdx.x; i < N4;
         i += gridDim.x * blockDim.x) {
        float4 a = reinterpret_cast<const float4*>(image)[i];
        float4 t = reinterpret_cast<const float4*>(target)[i];
        float dx = a.x - t.x, dy = a.y - t.y, dz = a.z - t.z, dw = a.w - t.w;
        s += dx * dx + dy * dy + dz * dz + dw * dw;
    }
#pragma unroll
    for (int o = 16; o > 0; o >>= 1) s += __shfl_xor_sync(0xffffffffu, s, o);
    __shared__ float warp_s[8];
    int wd = threadIdx.x >> 5, lane = threadIdx.x & 31;
    if (lane == 0) warp_s[wd] = s;
    __syncthreads();
    if (wd == 0) {
        s = (lane < (blockDim.x >> 5)) ? warp_s[lane] : 0.f;
#pragma unroll
        for (int o = 4; o > 0; o >>= 1) s += __shfl_xor_sync(0xffffffffu, s, o);
        if (lane == 0) atomicAdd(&g_img_sum, s);
    }
}

__global__ void k_txtloss(const float* __restrict__ text,
                          const float* __restrict__ target,
                          const int* __restrict__ pm) {
    int row = blockIdx.x * (blockDim.x >> 5) + (threadIdx.x >> 5);
    if (row >= NROWS) return;
    int lane = threadIdx.x & 31;
    int b = row / SQ, i = row % SQ;
    if (pm[b * SS + i + 1] != 0) return;
    int id = g_idx[row];
    const float4* pt = reinterpret_cast<const float4*>(
        text + (size_t)b * SS * DD + (size_t)(i + 1) * DD);
    const float4* pa = reinterpret_cast<const float4*>(
        target + (size_t)b * SS * DD + (size_t)(id + 1) * DD);
    float s = 0.f;
#pragma unroll
    for (int it = 0; it < DD / 128; it++) {
        float4 a = pt[lane + it * 32];
        float4 c = pa[lane + it * 32];
        float dx = a.x - c.x, dy = a.y - c.y, dz = a.z - c.z, dw = a.w - c.w;
        s += dx * dx + dy * dy + dz * dz + dw * dw;
    }
#pragma unroll
    for (int o = 16; o > 0; o >>= 1) s += __shfl_xor_sync(0xffffffffu, s, o);
    if (lane == 0) {
        atomicAdd(&g_txt_sum, s);
        atomicAdd(&g_valid, 1);
    }
}

__global__ void k_finalize(float* __restrict__ out) {
    float kt = g_txt_sum / ((float)g_valid * (float)DD);
    float ki = g_img_sum / (float)(BB * SS * DD);
    out[0] = 0.5f * (kt + ki);
    out[1] = kt;
    out[2] = ki;
}

__global__ void k_idxcopy(float* __restrict__ out) {
    int n = blockIdx.x * blockDim.x + threadIdx.x;
    if (n < NROWS) out[3 + n] = (float)g_idx[n];
}

// ============================ launch ============================

extern "C" void kernel_launch(void* const* d_in, const int* in_sizes, int n_in,
                              void* d_out, int out_size) {
    const float* image  = (const float*)d_in[0];
    const float* text   = (const float*)d_in[1];
    const float* target = (const float*)d_in[2];
    const int*   pm     = (const int*)d_in[3];
    float* out = (float*)d_out;

    k_init<<<1, 1>>>();
    k_prep_A<<<(BB * 512 * 96 + 255) / 256, 256>>>(text);
    k_prep_B<<<(BB * 512 * 96 + 255) / 256, 256>>>(target);
    k_invnorm<<<(NROWS + 3) / 4, 128>>>(target);

    cudaFuncSetAttribute(k_gemm, cudaFuncAttributeMaxDynamicSharedMemorySize, SMEM_DYN);
    k_gemm<<<dim3(16, BB), 256, SMEM_DYN>>>();

    k_merge<<<(NROWS + 255) / 256, 256>>>();
    k_rescore<<<256, 128>>>(text, target);
    k_imgloss<<<1184, 256>>>(image, target);
    k_txtloss<<<(NROWS + 3) / 4, 128>>>(text, target, pm);
    k_finalize<<<1, 1>>>(out);
    k_idxcopy<<<(NROWS + 255) / 256, 256>>>(out);
}

// round 6
// speedup vs baseline: 2.0831x; 2.0831x over previous
#include <cuda_runtime.h>
#include <cuda_bf16.h>
#include <cstdint>

#define BB 32
#define SS 512
#define DD 768
#define SQ 511
#define NROWS (BB*SQ)
#define NEG_INF __int_as_float(0xff800000)

#define CHUNKS 36          // K = 3*768 = 2304, chunks of 64
#define BLK_U4 1024        // 128 rows * 64 bf16 * 2B / 16B
#define TAU 2e-4f

// prepped tiles: [b][tile(0..3)][chunk][128 rows x 64 bf16, swizzled]
__device__ uint4 g_Apre[(size_t)BB * 4 * CHUNKS * BLK_U4];
__device__ uint4 g_Bpre[(size_t)BB * 4 * CHUNKS * BLK_U4];
__device__ float g_invn[NROWS];
__device__ float g_pv1[NROWS * 4];
__device__ int   g_pj1[NROWS * 4];
__device__ float g_pv2[NROWS * 4];
__device__ int   g_idx[NROWS];
__device__ int   g_queue[NROWS];
__device__ int   g_qcnt;
__device__ float g_txt_sum;
__device__ float g_img_sum;
__device__ int   g_valid;

__device__ __forceinline__ uint32_t smem_u32(const void* p) {
    uint32_t a;
    asm("{ .reg .u64 t; cvta.to.shared.u64 t, %1; cvt.u32.u64 %0, t; }"
        : "=r"(a) : "l"(p));
    return a;
}

// ============================ init ============================

__global__ void k_init() {
    g_txt_sum = 0.f; g_img_sum = 0.f; g_valid = 0; g_qcnt = 0;
}

// ============================ invnorm ============================

__global__ void k_invnorm(const float* __restrict__ target) {
    int row = blockIdx.x * (blockDim.x >> 5) + (threadIdx.x >> 5);
    if (row >= NROWS) return;
    int lane = threadIdx.x & 31;
    int b = row / SQ, j = row % SQ;
    const float4* p = reinterpret_cast<const float4*>(
        target + (size_t)b * SS * DD + (size_t)(j + 1) * DD);
    float s = 0.f;
#pragma unroll
    for (int it = 0; it < DD / 128; it++) {
        float4 v = p[lane + it * 32];
        s += v.x * v.x + v.y * v.y + v.z * v.z + v.w * v.w;
    }
#pragma unroll
    for (int o = 16; o > 0; o >>= 1) s += __shfl_xor_sync(0xffffffffu, s, o);
    if (lane == 0) g_invn[row] = rsqrtf(s);
}

// ============================ prep ============================
// 3 split groups: A = [hi, hi, mid], B = [hi, mid, hi] -> hh + hm + mh.

__device__ __forceinline__ uint4 pack8(const unsigned short* u) {
    uint4 v;
    v.x = (uint32_t)u[0] | ((uint32_t)u[1] << 16);
    v.y = (uint32_t)u[2] | ((uint32_t)u[3] << 16);
    v.z = (uint32_t)u[4] | ((uint32_t)u[5] << 16);
    v.w = (uint32_t)u[6] | ((uint32_t)u[7] << 16);
    return v;
}

__device__ __forceinline__ void split8(const float* x, uint4& vh, uint4& vm) {
    unsigned short h[8], m[8];
#pragma unroll
    for (int q = 0; q < 8; q++) {
        __nv_bfloat16 bh = __float2bfloat16(x[q]);
        float r1 = x[q] - __bfloat162float(bh);
        __nv_bfloat16 bm = __float2bfloat16(r1);
        h[q] = __bfloat16_as_ushort(bh);
        m[q] = __bfloat16_as_ushort(bm);
    }
    vh = pack8(h); vm = pack8(m);
}

__device__ __forceinline__ void prep_store(uint4* base, int r, int c, int kg, uint4 v) {
    int tile = r >> 7, row = r & 127;
    base[((size_t)tile * CHUNKS + c) * BLK_U4 + row * 8 + (kg ^ (row & 7))] = v;
}

__global__ void k_prep_A(const float* __restrict__ text) {
    int item = blockIdx.x * blockDim.x + threadIdx.x;   // BB*512*96
    if (item >= BB * 512 * 96) return;
    int ks = item % 96;
    int r  = (item / 96) & 511;
    int b  = item / (96 * 512);
    float x[8];
    if (r < SQ) {
        const float* src = text + ((size_t)b * SS + r + 1) * DD + ks * 8;
#pragma unroll
        for (int q = 0; q < 8; q++) x[q] = src[q];
    } else {
#pragma unroll
        for (int q = 0; q < 8; q++) x[q] = 0.f;
    }
    uint4 vh, vm;
    split8(x, vh, vm);
    uint4* base = g_Apre + (size_t)b * 4 * CHUNKS * BLK_U4;
#pragma unroll
    for (int g = 0; g < 3; g++) {
        uint4 v = (g < 2) ? vh : vm;      // A: hi, hi, mid
        int k6 = g * DD + ks * 8;
        prep_store(base, r, k6 >> 6, (k6 & 63) >> 3, v);
    }
}

__global__ void k_prep_B(const float* __restrict__ target) {
    int item = blockIdx.x * blockDim.x + threadIdx.x;
    if (item >= BB * 512 * 96) return;
    int ks = item % 96;
    int r  = (item / 96) & 511;
    int b  = item / (96 * 512);
    float x[8];
    if (r < SQ) {
        const float* src = target + ((size_t)b * SS + r + 1) * DD + ks * 8;
#pragma unroll
        for (int q = 0; q < 8; q++) x[q] = src[q];
    } else {
#pragma unroll
        for (int q = 0; q < 8; q++) x[q] = 0.f;
    }
    uint4 vh, vm;
    split8(x, vh, vm);
    uint4* base = g_Bpre + (size_t)b * 4 * CHUNKS * BLK_U4;
#pragma unroll
    for (int g = 0; g < 3; g++) {
        uint4 v = (g == 1) ? vm : vh;     // B: hi, mid, hi
        int k6 = g * DD + ks * 8;
        prep_store(base, r, k6 >> 6, (k6 & 63) >> 3, v);
    }
}

// ============================ GEMM + top-2 argmax ============================
// CTA: 128x128 tile; 8 warps of 64x32; BK=64 double-buffered cp.async.
// grid: x = itile*4 + jtile (16), y = b (32).

#define SMEM_DYN (65536 + 512)

#define LDSM_X4(r0, r1, r2, r3, addr) \
    asm volatile("ldmatrix.sync.aligned.m8n8.x4.shared.b16 {%0,%1,%2,%3}, [%4];" \
                 : "=r"(r0), "=r"(r1), "=r"(r2), "=r"(r3) : "r"(addr))

#define MMA16816(c, a, b0, b1) \
    asm volatile("mma.sync.aligned.m16n8k16.row.col.f32.bf16.bf16.f32 " \
                 "{%0,%1,%2,%3}, {%4,%5,%6,%7}, {%8,%9}, {%0,%1,%2,%3};" \
                 : "+f"((c)[0]), "+f"((c)[1]), "+f"((c)[2]), "+f"((c)[3]) \
                 : "r"((a)[0]), "r"((a)[1]), "r"((a)[2]), "r"((a)[3]), \
                   "r"(b0), "r"(b1))

__global__ __launch_bounds__(256, 2) void k_gemm() {
    extern __shared__ __align__(16) char sm[];
    uint32_t smb = smem_u32(sm);
    int tid = threadIdx.x, lane = tid & 31, wid = tid >> 5;
    int bx = blockIdx.x;
    int itile = bx >> 2, jtile = bx & 3;
    int b = blockIdx.y;
    int warpM = (wid & 1) * 64, warpN = (wid >> 1) * 32;

    float* Inv = (float*)(sm + 65536);
    if (tid < 128) {
        int j = jtile * 128 + tid;
        Inv[tid] = (j < SQ) ? g_invn[b * SQ + j] : 0.f;
    }

    const char* Asrc = (const char*)(g_Apre + (size_t)(b * 4 + itile) * CHUNKS * BLK_U4);
    const char* Bsrc = (const char*)(g_Bpre + (size_t)(b * 4 + jtile) * CHUNKS * BLK_U4);

    float acc[4][4][4];
#pragma unroll
    for (int mt = 0; mt < 4; mt++)
#pragma unroll
        for (int n8 = 0; n8 < 4; n8++)
#pragma unroll
            for (int e = 0; e < 4; e++) acc[mt][n8][e] = 0.f;

#define STAGE_COPY(c, s) do {                                                   \
    uint32_t dA = smb + (s) * 32768 + tid * 16;                                 \
    const char* gA = Asrc + (size_t)(c) * 16384 + tid * 16;                     \
    const char* gB = Bsrc + (size_t)(c) * 16384 + tid * 16;                     \
    _Pragma("unroll")                                                           \
    for (int it = 0; it < 4; it++) {                                            \
        asm volatile("cp.async.cg.shared.global [%0], [%1], 16;"                \
                     :: "r"(dA + it * 4096), "l"(gA + it * 4096));              \
        asm volatile("cp.async.cg.shared.global [%0], [%1], 16;"                \
                     :: "r"(dA + 16384 + it * 4096), "l"(gB + it * 4096));      \
    }                                                                           \
    asm volatile("cp.async.commit_group;");                                     \
} while (0)

    STAGE_COPY(0, 0);
    STAGE_COPY(1, 1);

    int lrow = lane & 15, khalf = lane >> 4;
    int bg8 = lane >> 3, bl8 = lane & 7;
    int bRow0 = warpN + ((bg8 >> 1) << 3) + bl8;
    int bKg = bg8 & 1;

    for (int c = 0; c < CHUNKS; c++) {
        if (c < CHUNKS - 1) asm volatile("cp.async.wait_group 1;");
        else                asm volatile("cp.async.wait_group 0;");
        __syncthreads();
        uint32_t aB = smb + (c & 1) * 32768;
        uint32_t bBs = aB + 16384;
#pragma unroll
        for (int ks = 0; ks < 4; ks++) {
            uint32_t a[4][4];
#pragma unroll
            for (int mt = 0; mt < 4; mt++) {
                int row = warpM + mt * 16 + lrow;
                int kg  = ks * 2 + khalf;
                uint32_t ad = aB + row * 128 + ((kg ^ (row & 7)) << 4);
                LDSM_X4(a[mt][0], a[mt][1], a[mt][2], a[mt][3], ad);
            }
            uint32_t bb[2][4];
#pragma unroll
            for (int nb = 0; nb < 2; nb++) {
                int row = bRow0 + nb * 16;
                int kg  = ks * 2 + bKg;
                uint32_t ad = bBs + row * 128 + ((kg ^ (row & 7)) << 4);
                LDSM_X4(bb[nb][0], bb[nb][1], bb[nb][2], bb[nb][3], ad);
            }
#pragma unroll
            for (int mt = 0; mt < 4; mt++)
#pragma unroll
                for (int n8 = 0; n8 < 4; n8++)
                    MMA16816(acc[mt][n8], a[mt],
                             bb[n8 >> 1][(n8 & 1) * 2],
                             bb[n8 >> 1][(n8 & 1) * 2 + 1]);
        }
        __syncthreads();
        if (c + 2 < CHUNKS) STAGE_COPY(c + 2, c & 1);
    }
#undef STAGE_COPY

    // epilogue: per-row top-2 within this 128-j tile, no atomics.
    float* sv1 = (float*)sm;             // [128][4]
    int*   sj1 = (int*)(sm + 2048);      // [128][4]
    float* sv2 = (float*)(sm + 4096);    // [128][4]

    int gid = lane >> 2, tig = lane & 3;
#pragma unroll
    for (int mt = 0; mt < 4; mt++) {
#pragma unroll
        for (int rh = 0; rh < 2; rh++) {
            int iloc = warpM + mt * 16 + gid + rh * 8;
            float v1 = NEG_INF, v2 = NEG_INF;
            int j1 = 1 << 30;
#pragma unroll
            for (int n8 = 0; n8 < 4; n8++) {
#pragma unroll
                for (int e = 0; e < 2; e++) {
                    int jloc = warpN + n8 * 8 + tig * 2 + e;
                    int j = jtile * 128 + jloc;
                    float v = (j < SQ) ? acc[mt][n8][rh * 2 + e] * Inv[jloc]
                                       : NEG_INF;
                    if (v > v1) { v2 = v1; v1 = v; j1 = j; }
                    else if (v > v2) v2 = v;
                }
            }
#pragma unroll
            for (int o = 1; o <= 2; o <<= 1) {
                float ov1 = __shfl_xor_sync(0xffffffffu, v1, o);
                float ov2 = __shfl_xor_sync(0xffffffffu, v2, o);
                int   oj  = __shfl_xor_sync(0xffffffffu, j1, o);
                if (ov1 > v1 || (ov1 == v1 && oj < j1)) {
                    v2 = fmaxf(v1, ov2); v1 = ov1; j1 = oj;
                } else {
                    v2 = fmaxf(v2, ov1);
                }
            }
            if (tig == 0) {
                int s = iloc * 4 + (wid >> 1);
                sv1[s] = v1; sj1[s] = j1; sv2[s] = v2;
            }
        }
    }
    __syncthreads();

    if (tid < 128) {
        float v1 = NEG_INF, v2 = NEG_INF;
        int j1 = 1 << 30;
#pragma unroll
        for (int q = 0; q < 4; q++) {
            float a1 = sv1[tid * 4 + q];
            float a2 = sv2[tid * 4 + q];
            int   aj = sj1[tid * 4 + q];
            if (a1 > v1 || (a1 == v1 && aj < j1)) {
                v2 = fmaxf(v1, a2); v1 = a1; j1 = aj;
            } else {
                v2 = fmaxf(v2, a1);
            }
        }
        int i = itile * 128 + tid;
        if (i < SQ) {
            int s = (b * SQ + i) * 4 + jtile;
            g_pv1[s] = v1; g_pj1[s] = j1; g_pv2[s] = v2;
        }
    }
}

// merge 4 jtile partials per row; enqueue ambiguous rows.
__global__ void k_merge() {
    int n = blockIdx.x * blockDim.x + threadIdx.x;
    if (n >= NROWS) return;
    float v1 = NEG_INF, v2 = NEG_INF;
    int j1 = 1 << 30;
#pragma unroll
    for (int q = 0; q < 4; q++) {
        float a1 = g_pv1[n * 4 + q];
        float a2 = g_pv2[n * 4 + q];
        int   aj = g_pj1[n * 4 + q];
        if (a1 > v1 || (a1 == v1 && aj < j1)) {
            v2 = fmaxf(v1, a2); v1 = a1; j1 = aj;
        } else {
            v2 = fmaxf(v2, a1);
        }
    }
    g_idx[n] = j1;
    if (v1 - v2 < TAU) {
        int slot = atomicAdd(&g_qcnt, 1);
        g_queue[slot] = n;
    }
}

// exact fp32 rescore for ambiguous rows: one CTA (256 thr) per queue entry.
__global__ __launch_bounds__(256) void k_rescore(const float* __restrict__ text,
                                                 const float* __restrict__ target) {
    __shared__ float4 txs[DD / 4];
    __shared__ float wv[8];
    __shared__ int   wj[8];
    int cnt = g_qcnt;
    for (int q = blockIdx.x; q < cnt; q += gridDim.x) {
        int row = g_queue[q];
        int b = row / SQ, i = row % SQ;
        __syncthreads();
        {
            const float4* src = reinterpret_cast<const float4*>(
                text + ((size_t)b * SS + i + 1) * DD);
            for (int d = threadIdx.x; d < DD / 4; d += 256) txs[d] = src[d];
        }
        __syncthreads();
        int wd = threadIdx.x >> 5, lane = threadIdx.x & 31;
        float best = NEG_INF;
        int bj = 0;
        for (int j = wd; j < SQ; j += 8) {
            const float4* tg = reinterpret_cast<const float4*>(
                target + ((size_t)b * SS + j + 1) * DD);
            float s = 0.f;
#pragma unroll
            for (int it = 0; it < DD / 128; it++) {
                float4 a = txs[lane + it * 32];
                float4 c = tg[lane + it * 32];
                s += a.x * c.x + a.y * c.y + a.z * c.z + a.w * c.w;
            }
#pragma unroll
            for (int o = 16; o > 0; o >>= 1) s += __shfl_xor_sync(0xffffffffu, s, o);
            float v = s * g_invn[b * SQ + j];
            if (v > best) { best = v; bj = j; }
        }
        if (lane == 0) { wv[wd] = best; wj[wd] = bj; }
        __syncthreads();
        if (threadIdx.x == 0) {
            float B = wv[0]; int J = wj[0];
#pragma unroll
            for (int w = 1; w < 8; w++)
                if (wv[w] > B || (wv[w] == B && wj[w] < J)) { B = wv[w]; J = wj[w]; }
            g_idx[row] = J;
        }
    }
}

// ============================ losses ============================

__global__ void k_imgloss(const float* __restrict__ image,
                          const float* __restrict__ target) {
    const int N4 = BB * SS * DD / 4;
    float s = 0.f;
    for (int i = blockIdx.x * blockDim.x + threadIdx.x; i < N4;
         i += gridDim.x * blockDim.x) {
        float4 a = reinterpret_cast<const float4*>(image)[i];
        float4 t = reinterpret_cast<const float4*>(target)[i];
        float dx = a.x - t.x, dy = a.y - t.y, dz = a.z - t.z, dw = a.w - t.w;
        s += dx * dx + dy * dy + dz * dz + dw * dw;
    }
#pragma unroll
    for (int o = 16; o > 0; o >>= 1) s += __shfl_xor_sync(0xffffffffu, s, o);
    __shared__ float warp_s[8];
    int wd = threadIdx.x >> 5, lane = threadIdx.x & 31;
    if (lane == 0) warp_s[wd] = s;
    __syncthreads();
    if (wd == 0) {
        s = (lane < (blockDim.x >> 5)) ? warp_s[lane] : 0.f;
#pragma unroll
        for (int o = 4; o > 0; o >>= 1) s += __shfl_xor_sync(0xffffffffu, s, o);
        if (lane == 0) atomicAdd(&g_img_sum, s);
    }
}

__global__ void k_txtloss(const float* __restrict__ text,
                          const float* __restrict__ target,
                          const int* __restrict__ pm) {
    int row = blockIdx.x * (blockDim.x >> 5) + (threadIdx.x >> 5);
    if (row >= NROWS) return;
    int lane = threadIdx.x & 31;
    int b = row / SQ, i = row % SQ;
    if (pm[b * SS + i + 1] != 0) return;
    int id = g_idx[row];
    const float4* pt = reinterpret_cast<const float4*>(
        text + (size_t)b * SS * DD + (size_t)(i + 1) * DD);
    const float4* pa = reinterpret_cast<const float4*>(
        target + (size_t)b * SS * DD + (size_t)(id + 1) * DD);
    float s = 0.f;
#pragma unroll
    for (int it = 0; it < DD / 128; it++) {
        float4 a = pt[lane + it * 32];
        float4 c = pa[lane + it * 32];
        float dx = a.x - c.x, dy = a.y - c.y, dz = a.z - c.z, dw = a.w - c.w;
        s += dx * dx + dy * dy + dz * dz + dw * dw;
    }
#pragma unroll
    for (int o = 16; o > 0; o >>= 1) s += __shfl_xor_sync(0xffffffffu, s, o);
    if (lane == 0) {
        atomicAdd(&g_txt_sum, s);
        atomicAdd(&g_valid, 1);
    }
}

__global__ void k_finalize(float* __restrict__ out) {
    float kt = g_txt_sum / ((float)g_valid * (float)DD);
    float ki = g_img_sum / (float)(BB * SS * DD);
    out[0] = 0.5f * (kt + ki);
    out[1] = kt;
    out[2] = ki;
}

__global__ void k_idxcopy(float* __restrict__ out) {
    int n = blockIdx.x * blockDim.x + threadIdx.x;
    if (n < NROWS) out[3 + n] = (float)g_idx[n];
}

// ============================ launch ============================

extern "C" void kernel_launch(void* const* d_in, const int* in_sizes, int n_in,
                              void* d_out, int out_size) {
    const float* image  = (const float*)d_in[0];
    const float* text   = (const float*)d_in[1];
    const float* target = (const float*)d_in[2];
    const int*   pm     = (const int*)d_in[3];
    float* out = (float*)d_out;

    k_init<<<1, 1>>>();
    k_prep_A<<<(BB * 512 * 96 + 255) / 256, 256>>>(text);
    k_prep_B<<<(BB * 512 * 96 + 255) / 256, 256>>>(target);
    k_invnorm<<<(NROWS + 3) / 4, 128>>>(target);

    cudaFuncSetAttribute(k_gemm, cudaFuncAttributeMaxDynamicSharedMemorySize, SMEM_DYN);
    k_gemm<<<dim3(16, BB), 256, SMEM_DYN>>>();

    k_merge<<<(NROWS + 255) / 256, 256>>>();
    k_rescore<<<512, 256>>>(text, target);
    k_imgloss<<<1184, 256>>>(image, target);
    k_txtloss<<<(NROWS + 3) / 4, 128>>>(text, target, pm);
    k_finalize<<<1, 1>>>(out);
    k_idxcopy<<<(NROWS + 255) / 256, 256>>>(out);
}

// round 7
// speedup vs baseline: 2.1148x; 1.0152x over previous
#include <cuda_runtime.h>
#include <cuda_bf16.h>
#include <cstdint>

#define BB 32
#define SS 512
#define DD 768
#define SQ 511
#define NROWS (BB*SQ)
#define NEG_INF __int_as_float(0xff800000)

#define CHUNKS 36          // K = 3*768 = 2304, chunks of 64
#define BLK_U4 1024        // 128 rows * 64 bf16 * 2B / 16B
#define TAU 2e-4f

// prepped tiles: [b][tile(0..3)][chunk][128 rows x 64 bf16, swizzled]
__device__ uint4 g_Apre[(size_t)BB * 4 * CHUNKS * BLK_U4];
__device__ uint4 g_Bpre[(size_t)BB * 4 * CHUNKS * BLK_U4];
__device__ float g_invn[NROWS];
__device__ float g_pv1[NROWS * 4];
__device__ int   g_pj1[NROWS * 4];
__device__ float g_pv2[NROWS * 4];
__device__ int   g_idx[NROWS];
__device__ int   g_queue[NROWS];
__device__ int   g_qcnt;
__device__ float g_txt_sum;
__device__ float g_img_sum;
__device__ int   g_valid;

__device__ __forceinline__ uint32_t smem_u32(const void* p) {
    uint32_t a;
    asm("{ .reg .u64 t; cvta.to.shared.u64 t, %1; cvt.u32.u64 %0, t; }"
        : "=r"(a) : "l"(p));
    return a;
}

// ============================ invnorm (+ scalar init) ============================

__global__ void k_invnorm(const float* __restrict__ target) {
    if (blockIdx.x == 0 && threadIdx.x == 0) {
        g_txt_sum = 0.f; g_img_sum = 0.f; g_valid = 0; g_qcnt = 0;
    }
    int row = blockIdx.x * (blockDim.x >> 5) + (threadIdx.x >> 5);
    if (row >= NROWS) return;
    int lane = threadIdx.x & 31;
    int b = row / SQ, j = row % SQ;
    const float4* p = reinterpret_cast<const float4*>(
        target + (size_t)b * SS * DD + (size_t)(j + 1) * DD);
    float s = 0.f;
#pragma unroll
    for (int it = 0; it < DD / 128; it++) {
        float4 v = p[lane + it * 32];
        s += v.x * v.x + v.y * v.y + v.z * v.z + v.w * v.w;
    }
#pragma unroll
    for (int o = 16; o > 0; o >>= 1) s += __shfl_xor_sync(0xffffffffu, s, o);
    if (lane == 0) g_invn[row] = rsqrtf(s);
}

// ============================ prep ============================
// 3 split groups: A = [hi, hi, mid], B = [hi, mid, hi] -> hh + hm + mh.

__device__ __forceinline__ uint4 pack8(const unsigned short* u) {
    uint4 v;
    v.x = (uint32_t)u[0] | ((uint32_t)u[1] << 16);
    v.y = (uint32_t)u[2] | ((uint32_t)u[3] << 16);
    v.z = (uint32_t)u[4] | ((uint32_t)u[5] << 16);
    v.w = (uint32_t)u[6] | ((uint32_t)u[7] << 16);
    return v;
}

__device__ __forceinline__ void split8(const float* x, uint4& vh, uint4& vm) {
    unsigned short h[8], m[8];
#pragma unroll
    for (int q = 0; q < 8; q++) {
        __nv_bfloat16 bh = __float2bfloat16(x[q]);
        float r1 = x[q] - __bfloat162float(bh);
        __nv_bfloat16 bm = __float2bfloat16(r1);
        h[q] = __bfloat16_as_ushort(bh);
        m[q] = __bfloat16_as_ushort(bm);
    }
    vh = pack8(h); vm = pack8(m);
}

__device__ __forceinline__ void prep_store(uint4* base, int r, int c, int kg, uint4 v) {
    int tile = r >> 7, row = r & 127;
    base[((size_t)tile * CHUNKS + c) * BLK_U4 + row * 8 + (kg ^ (row & 7))] = v;
}

__global__ void k_prep_A(const float* __restrict__ text) {
    int item = blockIdx.x * blockDim.x + threadIdx.x;   // BB*512*96
    if (item >= BB * 512 * 96) return;
    int ks = item % 96;
    int r  = (item / 96) & 511;
    int b  = item / (96 * 512);
    float x[8];
    if (r < SQ) {
        const float* src = text + ((size_t)b * SS + r + 1) * DD + ks * 8;
#pragma unroll
        for (int q = 0; q < 8; q++) x[q] = src[q];
    } else {
#pragma unroll
        for (int q = 0; q < 8; q++) x[q] = 0.f;
    }
    uint4 vh, vm;
    split8(x, vh, vm);
    uint4* base = g_Apre + (size_t)b * 4 * CHUNKS * BLK_U4;
#pragma unroll
    for (int g = 0; g < 3; g++) {
        uint4 v = (g < 2) ? vh : vm;      // A: hi, hi, mid
        int k6 = g * DD + ks * 8;
        prep_store(base, r, k6 >> 6, (k6 & 63) >> 3, v);
    }
}

__global__ void k_prep_B(const float* __restrict__ target) {
    int item = blockIdx.x * blockDim.x + threadIdx.x;
    if (item >= BB * 512 * 96) return;
    int ks = item % 96;
    int r  = (item / 96) & 511;
    int b  = item / (96 * 512);
    float x[8];
    if (r < SQ) {
        const float* src = target + ((size_t)b * SS + r + 1) * DD + ks * 8;
#pragma unroll
        for (int q = 0; q < 8; q++) x[q] = src[q];
    } else {
#pragma unroll
        for (int q = 0; q < 8; q++) x[q] = 0.f;
    }
    uint4 vh, vm;
    split8(x, vh, vm);
    uint4* base = g_Bpre + (size_t)b * 4 * CHUNKS * BLK_U4;
#pragma unroll
    for (int g = 0; g < 3; g++) {
        uint4 v = (g == 1) ? vm : vh;     // B: hi, mid, hi
        int k6 = g * DD + ks * 8;
        prep_store(base, r, k6 >> 6, (k6 & 63) >> 3, v);
    }
}

// ============================ GEMM + top-2 argmax ============================
// CTA: 128x128 tile; 8 warps of 64x32; BK=64, 3-stage cp.async pipeline,
// register double-buffered ldmatrix. grid: x = itile*4 + jtile, y = b.

#define SMEM_DYN (3 * 32768 + 512)

#define LDSM_X4(r0, r1, r2, r3, addr) \
    asm volatile("ldmatrix.sync.aligned.m8n8.x4.shared.b16 {%0,%1,%2,%3}, [%4];" \
                 : "=r"(r0), "=r"(r1), "=r"(r2), "=r"(r3) : "r"(addr))

#define MMA16816(c, a, b0, b1) \
    asm volatile("mma.sync.aligned.m16n8k16.row.col.f32.bf16.bf16.f32 " \
                 "{%0,%1,%2,%3}, {%4,%5,%6,%7}, {%8,%9}, {%0,%1,%2,%3};" \
                 : "+f"((c)[0]), "+f"((c)[1]), "+f"((c)[2]), "+f"((c)[3]) \
                 : "r"((a)[0]), "r"((a)[1]), "r"((a)[2]), "r"((a)[3]), \
                   "r"(b0), "r"(b1))

__global__ __launch_bounds__(256, 2) void k_gemm() {
    extern __shared__ __align__(16) char sm[];
    uint32_t smb = smem_u32(sm);
    int tid = threadIdx.x, lane = tid & 31, wid = tid >> 5;
    int bx = blockIdx.x;
    int itile = bx >> 2, jtile = bx & 3;
    int b = blockIdx.y;
    int warpM = (wid & 1) * 64, warpN = (wid >> 1) * 32;

    float* Inv = (float*)(sm + 3 * 32768);
    if (tid < 128) {
        int j = jtile * 128 + tid;
        Inv[tid] = (j < SQ) ? g_invn[b * SQ + j] : 0.f;
    }

    const char* Asrc = (const char*)(g_Apre + (size_t)(b * 4 + itile) * CHUNKS * BLK_U4);
    const char* Bsrc = (const char*)(g_Bpre + (size_t)(b * 4 + jtile) * CHUNKS * BLK_U4);

    float acc[4][4][4];
#pragma unroll
    for (int mt = 0; mt < 4; mt++)
#pragma unroll
        for (int n8 = 0; n8 < 4; n8++)
#pragma unroll
            for (int e = 0; e < 4; e++) acc[mt][n8][e] = 0.f;

#define STAGE_COPY(c, s) do {                                                   \
    uint32_t dA = smb + (s) * 32768 + tid * 16;                                 \
    const char* gA = Asrc + (size_t)(c) * 16384 + tid * 16;                     \
    const char* gB = Bsrc + (size_t)(c) * 16384 + tid * 16;                     \
    _Pragma("unroll")                                                           \
    for (int it = 0; it < 4; it++) {                                            \
        asm volatile("cp.async.cg.shared.global [%0], [%1], 16;"                \
                     :: "r"(dA + it * 4096), "l"(gA + it * 4096));              \
        asm volatile("cp.async.cg.shared.global [%0], [%1], 16;"                \
                     :: "r"(dA + 16384 + it * 4096), "l"(gB + it * 4096));      \
    }                                                                           \
    asm volatile("cp.async.commit_group;");                                     \
} while (0)

    STAGE_COPY(0, 0);
    STAGE_COPY(1, 1);

    // A lane mapping
    int lrow = lane & 15, khalf = lane >> 4;
    int aRowTerm[4], aRowMask[4];
#pragma unroll
    for (int mt = 0; mt < 4; mt++) {
        int row = warpM + mt * 16 + lrow;
        aRowTerm[mt] = row * 128;
        aRowMask[mt] = row & 7;
    }
    // B lane mapping
    int bg8 = lane >> 3, bl8 = lane & 7;
    int bRow0 = warpN + ((bg8 >> 1) << 3) + bl8;
    int bKg = bg8 & 1;
    int bRowTerm[2], bRowMask[2];
#pragma unroll
    for (int nb = 0; nb < 2; nb++) {
        int row = bRow0 + nb * 16;
        bRowTerm[nb] = row * 128;
        bRowMask[nb] = row & 7;
    }

    for (int c = 0; c < CHUNKS; c++) {
        if (c + 1 < CHUNKS) asm volatile("cp.async.wait_group 1;");
        else                asm volatile("cp.async.wait_group 0;");
        __syncthreads();
        if (c + 2 < CHUNKS) STAGE_COPY(c + 2, (c + 2) % 3);

        uint32_t aB = smb + (c % 3) * 32768;
        uint32_t bBs = aB + 16384;

        uint32_t a[2][4][4];
        uint32_t bb[2][2][4];
        // prefetch ks = 0
#pragma unroll
        for (int nb = 0; nb < 2; nb++) {
            uint32_t ad = bBs + bRowTerm[nb] + ((bKg ^ bRowMask[nb]) << 4);
            LDSM_X4(bb[0][nb][0], bb[0][nb][1], bb[0][nb][2], bb[0][nb][3], ad);
        }
#pragma unroll
        for (int mt = 0; mt < 4; mt++) {
            uint32_t ad = aB + aRowTerm[mt] + ((khalf ^ aRowMask[mt]) << 4);
            LDSM_X4(a[0][mt][0], a[0][mt][1], a[0][mt][2], a[0][mt][3], ad);
        }
#pragma unroll
        for (int ks = 0; ks < 4; ks++) {
            int cur = ks & 1, nxt = cur ^ 1;
            if (ks < 3) {
                int kgA = (ks + 1) * 2 + khalf;
                int kgB = (ks + 1) * 2 + bKg;
#pragma unroll
                for (int nb = 0; nb < 2; nb++) {
                    uint32_t ad = bBs + bRowTerm[nb] + ((kgB ^ bRowMask[nb]) << 4);
                    LDSM_X4(bb[nxt][nb][0], bb[nxt][nb][1],
                            bb[nxt][nb][2], bb[nxt][nb][3], ad);
                }
#pragma unroll
                for (int mt = 0; mt < 4; mt++) {
                    uint32_t ad = aB + aRowTerm[mt] + ((kgA ^ aRowMask[mt]) << 4);
                    LDSM_X4(a[nxt][mt][0], a[nxt][mt][1],
                            a[nxt][mt][2], a[nxt][mt][3], ad);
                }
            }
#pragma unroll
            for (int mt = 0; mt < 4; mt++)
#pragma unroll
                for (int n8 = 0; n8 < 4; n8++)
                    MMA16816(acc[mt][n8], a[cur][mt],
                             bb[cur][n8 >> 1][(n8 & 1) * 2],
                             bb[cur][n8 >> 1][(n8 & 1) * 2 + 1]);
        }
    }
#undef STAGE_COPY

    // epilogue: per-row top-2 within this 128-j tile, no atomics.
    // sv/sj arrays live in stage-0 smem (last read at chunk CHUNKS-3; safe).
    float* sv1 = (float*)sm;             // [128][4]
    int*   sj1 = (int*)(sm + 2048);      // [128][4]
    float* sv2 = (float*)(sm + 4096);    // [128][4]

    int gid = lane >> 2, tig = lane & 3;
#pragma unroll
    for (int mt = 0; mt < 4; mt++) {
#pragma unroll
        for (int rh = 0; rh < 2; rh++) {
            int iloc = warpM + mt * 16 + gid + rh * 8;
            float v1 = NEG_INF, v2 = NEG_INF;
            int j1 = 1 << 30;
#pragma unroll
            for (int n8 = 0; n8 < 4; n8++) {
#pragma unroll
                for (int e = 0; e < 2; e++) {
                    int jloc = warpN + n8 * 8 + tig * 2 + e;
                    int j = jtile * 128 + jloc;
                    float v = (j < SQ) ? acc[mt][n8][rh * 2 + e] * Inv[jloc]
                                       : NEG_INF;
                    if (v > v1) { v2 = v1; v1 = v; j1 = j; }
                    else if (v > v2) v2 = v;
                }
            }
#pragma unroll
            for (int o = 1; o <= 2; o <<= 1) {
                float ov1 = __shfl_xor_sync(0xffffffffu, v1, o);
                float ov2 = __shfl_xor_sync(0xffffffffu, v2, o);
                int   oj  = __shfl_xor_sync(0xffffffffu, j1, o);
                if (ov1 > v1 || (ov1 == v1 && oj < j1)) {
                    v2 = fmaxf(v1, ov2); v1 = ov1; j1 = oj;
                } else {
                    v2 = fmaxf(v2, ov1);
                }
            }
            if (tig == 0) {
                int s = iloc * 4 + (wid >> 1);
                sv1[s] = v1; sj1[s] = j1; sv2[s] = v2;
            }
        }
    }
    __syncthreads();

    if (tid < 128) {
        float v1 = NEG_INF, v2 = NEG_INF;
        int j1 = 1 << 30;
#pragma unroll
        for (int q = 0; q < 4; q++) {
            float a1 = sv1[tid * 4 + q];
            float a2 = sv2[tid * 4 + q];
            int   aj = sj1[tid * 4 + q];
            if (a1 > v1 || (a1 == v1 && aj < j1)) {
                v2 = fmaxf(v1, a2); v1 = a1; j1 = aj;
            } else {
                v2 = fmaxf(v2, a1);
            }
        }
        int i = itile * 128 + tid;
        if (i < SQ) {
            int s = (b * SQ + i) * 4 + jtile;
            g_pv1[s] = v1; g_pj1[s] = j1; g_pv2[s] = v2;
        }
    }
}

// merge 4 jtile partials per row; enqueue ambiguous rows.
__global__ void k_merge() {
    int n = blockIdx.x * blockDim.x + threadIdx.x;
    if (n >= NROWS) return;
    float v1 = NEG_INF, v2 = NEG_INF;
    int j1 = 1 << 30;
#pragma unroll
    for (int q = 0; q < 4; q++) {
        float a1 = g_pv1[n * 4 + q];
        float a2 = g_pv2[n * 4 + q];
        int   aj = g_pj1[n * 4 + q];
        if (a1 > v1 || (a1 == v1 && aj < j1)) {
            v2 = fmaxf(v1, a2); v1 = a1; j1 = aj;
        } else {
            v2 = fmaxf(v2, a1);
        }
    }
    g_idx[n] = j1;
    if (v1 - v2 < TAU) {
        int slot = atomicAdd(&g_qcnt, 1);
        g_queue[slot] = n;
    }
}

// exact fp32 rescore for ambiguous rows: one CTA (256 thr) per queue entry.
__global__ __launch_bounds__(256) void k_rescore(const float* __restrict__ text,
                                                 const float* __restrict__ target) {
    __shared__ float4 txs[DD / 4];
    __shared__ float wv[8];
    __shared__ int   wj[8];
    int cnt = g_qcnt;
    for (int q = blockIdx.x; q < cnt; q += gridDim.x) {
        int row = g_queue[q];
        int b = row / SQ, i = row % SQ;
        __syncthreads();
        {
            const float4* src = reinterpret_cast<const float4*>(
                text + ((size_t)b * SS + i + 1) * DD);
            for (int d = threadIdx.x; d < DD / 4; d += 256) txs[d] = src[d];
        }
        __syncthreads();
        int wd = threadIdx.x >> 5, lane = threadIdx.x & 31;
        float best = NEG_INF;
        int bj = 0;
        for (int j = wd; j < SQ; j += 8) {
            const float4* tg = reinterpret_cast<const float4*>(
                target + ((size_t)b * SS + j + 1) * DD);
            float s = 0.f;
#pragma unroll
            for (int it = 0; it < DD / 128; it++) {
                float4 a = txs[lane + it * 32];
                float4 c = tg[lane + it * 32];
                s += a.x * c.x + a.y * c.y + a.z * c.z + a.w * c.w;
            }
#pragma unroll
            for (int o = 16; o > 0; o >>= 1) s += __shfl_xor_sync(0xffffffffu, s, o);
            float v = s * g_invn[b * SQ + j];
            if (v > best) { best = v; bj = j; }
        }
        if (lane == 0) { wv[wd] = best; wj[wd] = bj; }
        __syncthreads();
        if (threadIdx.x == 0) {
            float B = wv[0]; int J = wj[0];
#pragma unroll
            for (int w = 1; w < 8; w++)
                if (wv[w] > B || (wv[w] == B && wj[w] < J)) { B = wv[w]; J = wj[w]; }
            g_idx[row] = J;
        }
    }
}

// ============================ losses ============================

__global__ void k_imgloss(const float* __restrict__ image,
                          const float* __restrict__ target) {
    const int N4 = BB * SS * DD / 4;
    float s = 0.f;
    for (int i = blockIdx.x * blockDim.x + threadIdx.x; i < N4;
         i += gridDim.x * blockDim.x) {
        float4 a = reinterpret_cast<const float4*>(image)[i];
        float4 t = reinterpret_cast<const float4*>(target)[i];
        float dx = a.x - t.x, dy = a.y - t.y, dz = a.z - t.z, dw = a.w - t.w;
        s += dx * dx + dy * dy + dz * dz + dw * dw;
    }
#pragma unroll
    for (int o = 16; o > 0; o >>= 1) s += __shfl_xor_sync(0xffffffffu, s, o);
    __shared__ float warp_s[8];
    int wd = threadIdx.x >> 5, lane = threadIdx.x & 31;
    if (lane == 0) warp_s[wd] = s;
    __syncthreads();
    if (wd == 0) {
        s = (lane < (blockDim.x >> 5)) ? warp_s[lane] : 0.f;
#pragma unroll
        for (int o = 4; o > 0; o >>= 1) s += __shfl_xor_sync(0xffffffffu, s, o);
        if (lane == 0) atomicAdd(&g_img_sum, s);
    }
}

__global__ void k_txtloss(const float* __restrict__ text,
                          const float* __restrict__ target,
                          const int* __restrict__ pm) {
    int row = blockIdx.x * (blockDim.x >> 5) + (threadIdx.x >> 5);
    if (row >= NROWS) return;
    int lane = threadIdx.x & 31;
    int b = row / SQ, i = row % SQ;
    if (pm[b * SS + i + 1] != 0) return;
    int id = g_idx[row];
    const float4* pt = reinterpret_cast<const float4*>(
        text + (size_t)b * SS * DD + (size_t)(i + 1) * DD);
    const float4* pa = reinterpret_cast<const float4*>(
        target + (size_t)b * SS * DD + (size_t)(id + 1) * DD);
    float s = 0.f;
#pragma unroll
    for (int it = 0; it < DD / 128; it++) {
        float4 a = pt[lane + it * 32];
        float4 c = pa[lane + it * 32];
        float dx = a.x - c.x, dy = a.y - c.y, dz = a.z - c.z, dw = a.w - c.w;
        s += dx * dx + dy * dy + dz * dz + dw * dw;
    }
#pragma unroll
    for (int o = 16; o > 0; o >>= 1) s += __shfl_xor_sync(0xffffffffu, s, o);
    if (lane == 0) {
        atomicAdd(&g_txt_sum, s);
        atomicAdd(&g_valid, 1);
    }
}

__global__ void k_finalize(float* __restrict__ out) {
    float kt = g_txt_sum / ((float)g_valid * (float)DD);
    float ki = g_img_sum / (float)(BB * SS * DD);
    out[0] = 0.5f * (kt + ki);
    out[1] = kt;
    out[2] = ki;
}

__global__ void k_idxcopy(float* __restrict__ out) {
    int n = blockIdx.x * blockDim.x + threadIdx.x;
    if (n < NROWS) out[3 + n] = (float)g_idx[n];
}

// ============================ launch ============================

extern "C" void kernel_launch(void* const* d_in, const int* in_sizes, int n_in,
                              void* d_out, int out_size) {
    const float* image  = (const float*)d_in[0];
    const float* text   = (const float*)d_in[1];
    const float* target = (const float*)d_in[2];
    const int*   pm     = (const int*)d_in[3];
    float* out = (float*)d_out;

    k_invnorm<<<(NROWS + 3) / 4, 128>>>(target);
    k_prep_A<<<(BB * 512 * 96 + 255) / 256, 256>>>(text);
    k_prep_B<<<(BB * 512 * 96 + 255) / 256, 256>>>(target);

    cudaFuncSetAttribute(k_gemm, cudaFuncAttributeMaxDynamicSharedMemorySize, SMEM_DYN);
    k_gemm<<<dim3(16, BB), 256, SMEM_DYN>>>();

    k_merge<<<(NROWS + 255) / 256, 256>>>();
    k_rescore<<<512, 256>>>(text, target);
    k_imgloss<<<1184, 256>>>(image, target);
    k_txtloss<<<(NROWS + 3) / 4, 128>>>(text, target, pm);
    k_finalize<<<1, 1>>>(out);
    k_idxcopy<<<(NROWS + 255) / 256, 256>>>(out);
}